// round 11
// baseline (speedup 1.0000x reference)
#include <cuda_runtime.h>
#include <cstdint>
#include <cstddef>

// Problem constants
#define BB 4096
#define TT 128
#define FF 128
#define AA 384   // F + E + TD
#define GG 512   // 4F
#define BT_ (BB * TT)

// Scratch
__device__ float g_Z[(size_t)BT_ * GG];   // Z = X@Wi + bh (fp32, gate-permuted cols)
__device__ float g_WiR[(size_t)AA * GG];  // Wi, tf32-rna-rounded, original layout
__device__ float g_WhF[FF * GG];          // Wh packed in k2 fragment order (gate-aware)

// ---------------------------------------------------------------------------
// helpers
// ---------------------------------------------------------------------------
__device__ __forceinline__ float tf32r(float x) {
    uint32_t u;
    asm("cvt.rna.tf32.f32 %0, %1;" : "=r"(u) : "f"(x));
    return __uint_as_float(u);
}

__device__ __forceinline__ void mma8(float c[4], const uint32_t a[4], const uint32_t b[2]) {
    asm volatile(
        "mma.sync.aligned.m16n8k8.row.col.f32.tf32.tf32.f32 "
        "{%0,%1,%2,%3},{%4,%5,%6,%7},{%8,%9},{%0,%1,%2,%3};\n"
        : "+f"(c[0]), "+f"(c[1]), "+f"(c[2]), "+f"(c[3])
        : "r"(a[0]), "r"(a[1]), "r"(a[2]), "r"(a[3]), "r"(b[0]), "r"(b[1]));
}

__device__ __forceinline__ float tanhap(float x) {
    float y;
    asm("tanh.approx.f32 %0, %1;" : "=f"(y) : "f"(x));
    return y;
}
__device__ __forceinline__ float sigm_f(float x) {
    return fmaf(tanhap(0.5f * x), 0.5f, 0.5f);
}
#define tanh_f tanhap

__device__ __forceinline__ uint32_t smem_u32(const void* p) {
    uint32_t a;
    asm("{ .reg .u64 t; cvta.to.shared.u64 t, %1; cvt.u32.u64 %0, t; }" : "=r"(a) : "l"(p));
    return a;
}

__device__ __forceinline__ void cpasync16(uint32_t dst, const void* src) {
    asm volatile("cp.async.cg.shared.global [%0], [%1], 16;" :: "r"(dst), "l"(src));
}
__device__ __forceinline__ void cpcommit() {
    asm volatile("cp.async.commit_group;" ::: "memory");
}
template <int N>
__device__ __forceinline__ void cpwait() {
    asm volatile("cp.async.wait_group %0;" :: "n"(N) : "memory");
}

// ---------------------------------------------------------------------------
// alignment dummies: distinct names so the ncu -s window identifies itself
// ---------------------------------------------------------------------------
__global__ void dAlign1() {}
__global__ void dAlign2() {}
__global__ void dAlign3() {}
__global__ void dAlign4() {}

// ---------------------------------------------------------------------------
// k0: round Wi (rna) into g_WiR; pack Wh into k2 fragment order (gate-aware).
// g_WhF float2 at ((kk16*64 + w*8 + j)*32 + lane):
//   .x = Wh[kk16*8 + l4][n], .y = Wh[kk16*8 + 4 + l4][n]
//   n = (j>>1)*128 + w*16 + (j&1)*8 + g4
// ---------------------------------------------------------------------------
__global__ void k0_prep(const float* __restrict__ Wi, const float* __restrict__ Wh) {
    int i = blockIdx.x * blockDim.x + threadIdx.x;
    if (i < AA * GG) g_WiR[i] = tf32r(Wi[i]);
    if (i < FF * GG) {
        int kr  = i & 1;
        int l4  = (i >> 1) & 3;
        int ln  = (i >> 3) & 7;
        int n8  = (i >> 6) & 63;
        int kkb = (i >> 12) & 15;
        int w = n8 >> 3, j = n8 & 7;
        int k = kkb * 8 + kr * 4 + l4;
        int n = (j >> 1) * 128 + w * 16 + (j & 1) * 8 + ln;
        g_WhF[i] = tf32r(Wh[(size_t)k * GG + n]);
    }
}

// ---------------------------------------------------------------------------
// k1: Z[r, cperm(n)] = sum_k X[r,k]*Wi[k,n] + bh[n]
// CTA tile 128x256 (two gates per CTA -> A DRAM traffic halved vs 128x128),
// 512 threads, warp tile 32x64 (4m x 4n warps), BK=32,
// 3-deep cp.async pipeline (no partner CTA, so copies must self-hide).
// ---------------------------------------------------------------------------
#define A_STRIDE (128 * 36 * 4)
#define B_STRIDE (32 * 264 * 4)
#define B_BASE   (3 * A_STRIDE)
#define K1_SMEM  (3 * A_STRIDE + 3 * B_STRIDE)

__global__ __launch_bounds__(512, 1) void k1_gemm(
    const float* __restrict__ seq, const float* __restrict__ seq_e,
    const float* __restrict__ seq_t, const float* __restrict__ bh)
{
    extern __shared__ float dsm[];
    const uint32_t sb = smem_u32(dsm);

    const int m0 = (blockIdx.x >> 1) * 128;
    const int gx2 = blockIdx.x & 1;        // covers gates 2*gx2, 2*gx2+1
    const int n0 = gx2 * 256;
    const int tid = threadIdx.x;
    const int lane = tid & 31;
    const int warp = tid >> 5;             // 0..15
    const int wm = (warp >> 2) * 32;       // 4 m-slices of 32
    const int wn = (warp & 3) * 64;        // 4 n-slices of 64
    const int g4 = lane >> 2;
    const int l4 = lane & 3;

    // copy-thread mapping
    const int arow = tid >> 2;             // 0..127
    const int ac4  = tid & 3;
    const int brow = tid >> 4;             // 0..31
    const int bc4  = tid & 15;

    float acc[2][8][4];
    #pragma unroll
    for (int i = 0; i < 2; i++)
        #pragma unroll
        for (int j = 0; j < 8; j++)
            #pragma unroll
            for (int q = 0; q < 4; q++) acc[i][j][q] = 0.f;

    auto issue = [&](int c) {
        const int buf = c % 3;
        const float* Xs = (c < 4) ? seq : (c < 8) ? seq_e : seq_t;
        const int kb = (c & 3) * 32;
        #pragma unroll
        for (int i = 0; i < 2; i++) {
            int col = (ac4 + 4 * i) * 4;   // 0..28
            cpasync16(sb + buf * A_STRIDE + (arow * 36 + col) * 4,
                      Xs + (size_t)(m0 + arow) * FF + kb + col);
        }
        #pragma unroll
        for (int i = 0; i < 4; i++) {
            int col = (bc4 + 16 * i) * 4;  // 0..252
            cpasync16(sb + B_BASE + buf * B_STRIDE + (brow * 264 + col) * 4,
                      g_WiR + (size_t)(c * 32 + brow) * GG + n0 + col);
        }
        cpcommit();
    };

    issue(0);
    issue(1);
    cpwait<1>();            // chunk 0 complete (chunk 1 may be in flight)
    __syncthreads();

    for (int c = 0; c < 12; c++) {
        if (c + 2 < 12) issue(c + 2);      // overlapped with mma below

        const float* As = dsm + (c % 3) * (A_STRIDE / 4);
        const float* Bs = dsm + (B_BASE / 4) + (c % 3) * (B_STRIDE / 4);
        #pragma unroll
        for (int k8 = 0; k8 < 32; k8 += 8) {
            uint32_t af[2][4];
            #pragma unroll
            for (int i = 0; i < 2; i++) {
                int row = wm + i * 16 + g4;
                int col = k8 + l4;
                af[i][0] = __float_as_uint(As[row * 36 + col]);
                af[i][1] = __float_as_uint(As[(row + 8) * 36 + col]);
                af[i][2] = __float_as_uint(As[row * 36 + col + 4]);
                af[i][3] = __float_as_uint(As[(row + 8) * 36 + col + 4]);
            }
            uint32_t bf2[8][2];
            #pragma unroll
            for (int j = 0; j < 8; j++) {
                int nn = wn + j * 8 + g4;
                bf2[j][0] = __float_as_uint(Bs[(k8 + l4) * 264 + nn]);
                bf2[j][1] = __float_as_uint(Bs[(k8 + 4 + l4) * 264 + nn]);
            }
            #pragma unroll
            for (int i = 0; i < 2; i++)
                #pragma unroll
                for (int j = 0; j < 8; j++)
                    mma8(acc[i][j], af[i], bf2[j]);
        }
        if (c + 1 < 12) {
            if (c + 2 < 12) cpwait<1>(); else cpwait<0>();   // chunk c+1 complete
            __syncthreads();
        }
    }

    // epilogue: + bh, gate-permuted column store
    // f in [0,256): gate = gx2*2 + (f>>7), feat = f&127
    // cperm = (feat>>4)*64 + (gate*2 + ((feat>>3)&1))*8 + (feat&7)
    #pragma unroll
    for (int i = 0; i < 2; i++) {
        int gr = m0 + wm + i * 16 + g4;
        #pragma unroll
        for (int j = 0; j < 8; j++) {
            int f = wn + j * 8 + l4 * 2;
            int gate = gx2 * 2 + (f >> 7);
            int feat = f & 127;
            int cperm = (feat >> 4) * 64 + (gate * 2 + ((feat >> 3) & 1)) * 8 + (feat & 7);
            float bv0 = bh[gate * 128 + feat], bv1 = bh[gate * 128 + feat + 1];
            float2 v0 = make_float2(acc[i][j][0] + bv0, acc[i][j][1] + bv1);
            float2 v1 = make_float2(acc[i][j][2] + bv0, acc[i][j][3] + bv1);
            *(float2*)(g_Z + (size_t)gr * GG + cperm) = v0;
            *(float2*)(g_Z + (size_t)(gr + 8) * GG + cperm) = v1;
        }
    }
}

// ---------------------------------------------------------------------------
// k2: recurrent LSTM, 32 batch rows per CTA, register gates, c in registers,
// h double-buffered in SMEM (1 barrier/step), Wh register-double-buffered,
// Z rows prefetched one step ahead.
// ---------------------------------------------------------------------------
#define K2_SMEM ((2 * 32 * 132 + 32 * 128 + 32 * 128) * 4)

__global__ __launch_bounds__(256, 1) void k2_lstm(
    const float* __restrict__ src,
    const float* __restrict__ W1, const float* __restrict__ b1,
    const float* __restrict__ W2, const float* __restrict__ b2,
    float* __restrict__ out)
{
    extern __shared__ float sm[];
    float* h2 = sm;                   // 2 buffers of 32 x 132
    float* s_src = sm + 2 * 32 * 132; // 32 x 128
    float* s_hid = s_src + 32 * 128;  // 32 x 128

    const int b0 = blockIdx.x * 32;
    const int tid = threadIdx.x;
    const int lane = tid & 31;
    const int warp = tid >> 5;
    const int g4 = lane >> 2;
    const int l4 = lane & 3;

    for (int p = tid; p < 32 * 132; p += 256) h2[p] = 0.f;  // buf0 = h(-1) = 0
    __syncthreads();

    const float2* whf = (const float2*)g_WhF;
    const int wbase = warp * 8;   // n8 base for this warp

    float c_reg[2][2][4];
    #pragma unroll
    for (int i = 0; i < 2; i++)
        #pragma unroll
        for (int jh = 0; jh < 2; jh++)
            #pragma unroll
            for (int q = 0; q < 4; q++) c_reg[i][jh][q] = 0.f;

    // Z prefetch registers (step t's values, loaded during step t-1)
    float2 zreg[2][8][2];
    #pragma unroll
    for (int i = 0; i < 2; i++) {
        const float* z0 = g_Z + ((size_t)(b0 + i * 16 + g4) * TT + 0) * GG + warp * 64;
        const float* z1 = g_Z + ((size_t)(b0 + i * 16 + g4 + 8) * TT + 0) * GG + warp * 64;
        #pragma unroll
        for (int j = 0; j < 8; j++) {
            zreg[i][j][0] = *(const float2*)(z0 + j * 8 + l4 * 2);
            zreg[i][j][1] = *(const float2*)(z1 + j * 8 + l4 * 2);
        }
    }

    for (int t = 0; t < TT; t++) {
        const float* hcur = h2 + (t & 1) * (32 * 132);
        float* hnxt = h2 + ((t + 1) & 1) * (32 * 132);

        // --- acc init from prefetched Z ---
        float acc[2][8][4];
        #pragma unroll
        for (int i = 0; i < 2; i++)
            #pragma unroll
            for (int j = 0; j < 8; j++) {
                acc[i][j][0] = zreg[i][j][0].x; acc[i][j][1] = zreg[i][j][0].y;
                acc[i][j][2] = zreg[i][j][1].x; acc[i][j][3] = zreg[i][j][1].y;
            }

        // --- issue Z prefetch for next step (hidden under the mma loop) ---
        {
            const int tn = (t + 1 < TT) ? t + 1 : TT - 1;
            #pragma unroll
            for (int i = 0; i < 2; i++) {
                const float* z0 = g_Z + ((size_t)(b0 + i * 16 + g4) * TT + tn) * GG + warp * 64;
                const float* z1 = g_Z + ((size_t)(b0 + i * 16 + g4 + 8) * TT + tn) * GG + warp * 64;
                #pragma unroll
                for (int j = 0; j < 8; j++) {
                    zreg[i][j][0] = *(const float2*)(z0 + j * 8 + l4 * 2);
                    zreg[i][j][1] = *(const float2*)(z1 + j * 8 + l4 * 2);
                }
            }
        }

        // --- z += h @ Wh, Wh register-double-buffered ---
        float2 wreg[8];
        #pragma unroll
        for (int j = 0; j < 8; j++)
            wreg[j] = whf[(size_t)(wbase + j) * 32 + lane];

        #pragma unroll
        for (int kk16 = 0; kk16 < 16; kk16++) {
            float2 wnxt[8];
            if (kk16 < 15) {
                #pragma unroll
                for (int j = 0; j < 8; j++)
                    wnxt[j] = whf[(size_t)((kk16 + 1) * 64 + wbase + j) * 32 + lane];
            }
            const int kk = kk16 * 8;
            uint32_t af[2][4];
            #pragma unroll
            for (int i = 0; i < 2; i++) {
                int row = i * 16 + g4;
                af[i][0] = __float_as_uint(hcur[row * 132 + kk + l4]);
                af[i][1] = __float_as_uint(hcur[(row + 8) * 132 + kk + l4]);
                af[i][2] = __float_as_uint(hcur[row * 132 + kk + 4 + l4]);
                af[i][3] = __float_as_uint(hcur[(row + 8) * 132 + kk + 4 + l4]);
            }
            #pragma unroll
            for (int j = 0; j < 8; j++) {
                uint32_t bf2[2] = { __float_as_uint(wreg[j].x), __float_as_uint(wreg[j].y) };
                mma8(acc[0][j], af[0], bf2);
                mma8(acc[1][j], af[1], bf2);
            }
            if (kk16 < 15) {
                #pragma unroll
                for (int j = 0; j < 8; j++) wreg[j] = wnxt[j];
            }
        }

        // --- gates in registers: j = gate*2 + jh ---
        #pragma unroll
        for (int i = 0; i < 2; i++) {
            int r0 = i * 16 + g4;
            #pragma unroll
            for (int jh = 0; jh < 2; jh++) {
                float hv[4];
                #pragma unroll
                for (int q = 0; q < 4; q++) {
                    float zi = acc[i][0 + jh][q];
                    float zf = acc[i][2 + jh][q];
                    float zg = acc[i][4 + jh][q];
                    float zo = acc[i][6 + jh][q];
                    float co = c_reg[i][jh][q];
                    float cn = sigm_f(zf) * co + sigm_f(zi) * tanh_f(zg);
                    hv[q] = sigm_f(zo) * tanh_f(cn);
                    c_reg[i][jh][q] = cn;
                }
                int fb = warp * 16 + jh * 8 + l4 * 2;
                *(float2*)(hnxt + r0 * 132 + fb) =
                    make_float2(tf32r(hv[0]), tf32r(hv[1]));
                *(float2*)(hnxt + (r0 + 8) * 132 + fb) =
                    make_float2(tf32r(hv[2]), tf32r(hv[3]));
            }
        }
        __syncthreads();
    }

    // ---------------- fused merge MLP: out = relu([hn|src]@W1+b1)@W2+b2 ----
    const float* hfin = h2;  // t=127 wrote buffer 0
    for (int p = tid; p < 32 * 128; p += 256) {
        int row = p >> 7, fc = p & 127;
        s_src[p] = src[(size_t)(b0 + row) * FF + fc];
    }
    __syncthreads();

    const int col = tid & 127;
    const int rb = (tid >> 7) * 16;
    float a1[16];
    #pragma unroll
    for (int r = 0; r < 16; r++) a1[r] = b1[col];
    for (int k = 0; k < 128; k++) {
        float wv = W1[k * 128 + col];
        #pragma unroll
        for (int r = 0; r < 16; r++) a1[r] += hfin[(rb + r) * 132 + k] * wv;
    }
    for (int k = 0; k < 128; k++) {
        float wv = W1[(128 + k) * 128 + col];
        #pragma unroll
        for (int r = 0; r < 16; r++) a1[r] += s_src[(rb + r) * 128 + k] * wv;
    }
    #pragma unroll
    for (int r = 0; r < 16; r++) a1[r] = fmaxf(a1[r], 0.f);

    #pragma unroll
    for (int r = 0; r < 16; r++) s_hid[(rb + r) * 128 + col] = a1[r];
    __syncthreads();

    float a2[16];
    #pragma unroll
    for (int r = 0; r < 16; r++) a2[r] = b2[col];
    for (int k = 0; k < 128; k++) {
        float wv = W2[k * 128 + col];
        #pragma unroll
        for (int r = 0; r < 16; r++) a2[r] += s_hid[(rb + r) * 128 + k] * wv;
    }
    #pragma unroll
    for (int r = 0; r < 16; r++)
        out[(size_t)(b0 + rb + r) * FF + col] = a2[r];
}

// ---------------------------------------------------------------------------
// launch
// inputs: 0 src, 1 src_t(unused), 2 seq, 3 seq_t, 4 seq_e, 5 mask(unused),
//         6 Wi, 7 Wh, 8 bh, 9 W1, 10 b1, 11 W2, 12 b2
// ---------------------------------------------------------------------------
extern "C" void kernel_launch(void* const* d_in, const int* in_sizes, int n_in,
                              void* d_out, int out_size)
{
    const float* src   = (const float*)d_in[0];
    const float* seq   = (const float*)d_in[2];
    const float* seq_t = (const float*)d_in[3];
    const float* seq_e = (const float*)d_in[4];
    const float* Wi    = (const float*)d_in[6];
    const float* Wh    = (const float*)d_in[7];
    const float* bh    = (const float*)d_in[8];
    const float* W1    = (const float*)d_in[9];
    const float* b1    = (const float*)d_in[10];
    const float* W2    = (const float*)d_in[11];
    const float* b2    = (const float*)d_in[12];
    float* out = (float*)d_out;

    // alignment probes: shift the ncu -s window; the captured name tells us
    // the launch-count arithmetic so the next round can target k1/k2.
    dAlign1<<<1, 32>>>();
    dAlign2<<<1, 32>>>();
    dAlign3<<<1, 32>>>();
    dAlign4<<<1, 32>>>();

    k0_prep<<<(AA * GG + 255) / 256, 256>>>(Wi, Wh);

    cudaFuncSetAttribute(k1_gemm, cudaFuncAttributeMaxDynamicSharedMemorySize, K1_SMEM);
    k1_gemm<<<(BT_ / 128) * 2, 512, K1_SMEM>>>(seq, seq_e, seq_t, bh);

    cudaFuncSetAttribute(k2_lstm, cudaFuncAttributeMaxDynamicSharedMemorySize, K2_SMEM);
    k2_lstm<<<BB / 32, 256, K2_SMEM>>>(src, W1, b1, W2, b2, out);
}

// round 13
// speedup vs baseline: 1.0377x; 1.0377x over previous
#include <cuda_runtime.h>
#include <cstdint>
#include <cstddef>

// Problem constants
#define BB 4096
#define TT 128
#define FF 128
#define AA 384   // F + E + TD
#define GG 512   // 4F
#define BT_ (BB * TT)

// Scratch
__device__ float g_Z[(size_t)BT_ * GG];   // Z = X@Wi + bh (fp32, gate-permuted cols)
__device__ float g_WiR[(size_t)AA * GG];  // Wi, tf32-rna-rounded, original layout
__device__ float g_WhF[FF * GG];          // Wh packed in k2 fragment order (gate-aware)

// ---------------------------------------------------------------------------
// helpers
// ---------------------------------------------------------------------------
__device__ __forceinline__ float tf32r(float x) {
    uint32_t u;
    asm("cvt.rna.tf32.f32 %0, %1;" : "=r"(u) : "f"(x));
    return __uint_as_float(u);
}

__device__ __forceinline__ void mma8(float c[4], const uint32_t a[4], const uint32_t b[2]) {
    asm volatile(
        "mma.sync.aligned.m16n8k8.row.col.f32.tf32.tf32.f32 "
        "{%0,%1,%2,%3},{%4,%5,%6,%7},{%8,%9},{%0,%1,%2,%3};\n"
        : "+f"(c[0]), "+f"(c[1]), "+f"(c[2]), "+f"(c[3])
        : "r"(a[0]), "r"(a[1]), "r"(a[2]), "r"(a[3]), "r"(b[0]), "r"(b[1]));
}

__device__ __forceinline__ float tanhap(float x) {
    float y;
    asm("tanh.approx.f32 %0, %1;" : "=f"(y) : "f"(x));
    return y;
}
__device__ __forceinline__ float sigm_f(float x) {
    return fmaf(tanhap(0.5f * x), 0.5f, 0.5f);
}
#define tanh_f tanhap

__device__ __forceinline__ uint32_t smem_u32(const void* p) {
    uint32_t a;
    asm("{ .reg .u64 t; cvta.to.shared.u64 t, %1; cvt.u32.u64 %0, t; }" : "=r"(a) : "l"(p));
    return a;
}

__device__ __forceinline__ void cpasync16(uint32_t dst, const void* src) {
    asm volatile("cp.async.cg.shared.global [%0], [%1], 16;" :: "r"(dst), "l"(src));
}
__device__ __forceinline__ void cpcommit() {
    asm volatile("cp.async.commit_group;" ::: "memory");
}
template <int N>
__device__ __forceinline__ void cpwait() {
    asm volatile("cp.async.wait_group %0;" :: "n"(N) : "memory");
}

// ---------------------------------------------------------------------------
// alignment dummies: capture slot = 4th launch -> order d1,d2,k0 puts k1 there
// ---------------------------------------------------------------------------
__global__ void dAlign1() {}
__global__ void dAlign2() {}

// ---------------------------------------------------------------------------
// k0: round Wi (rna) into g_WiR; pack Wh into k2 fragment order (gate-aware).
// g_WhF float2 at ((kk16*64 + w*8 + j)*32 + lane):
//   .x = Wh[kk16*8 + l4][n], .y = Wh[kk16*8 + 4 + l4][n]
//   n = (j>>1)*128 + w*16 + (j&1)*8 + g4
// ---------------------------------------------------------------------------
__global__ void k0_prep(const float* __restrict__ Wi, const float* __restrict__ Wh) {
    int i = blockIdx.x * blockDim.x + threadIdx.x;
    if (i < AA * GG) g_WiR[i] = tf32r(Wi[i]);
    if (i < FF * GG) {
        int kr  = i & 1;
        int l4  = (i >> 1) & 3;
        int ln  = (i >> 3) & 7;
        int n8  = (i >> 6) & 63;
        int kkb = (i >> 12) & 15;
        int w = n8 >> 3, j = n8 & 7;
        int k = kkb * 8 + kr * 4 + l4;
        int n = (j >> 1) * 128 + w * 16 + (j & 1) * 8 + ln;
        g_WhF[i] = tf32r(Wh[(size_t)k * GG + n]);
    }
}

// ---------------------------------------------------------------------------
// k1: Z[r, cperm(n)] = sum_k X[r,k]*Wi[k,n] + bh[n]
// R10 geometry (proven fastest): CTA tile 128x128 (n-tile = one gate), BK=32,
// 256 threads, 2 CTAs/SM. Upgraded: 3-deep cp.async pipeline so each copy
// gets two mma-phases of slack instead of one.
// ---------------------------------------------------------------------------
#define A_STRIDE (128 * 36 * 4)
#define B_STRIDE (32 * 132 * 4)
#define B_BASE   (3 * A_STRIDE)
#define K1_SMEM  (3 * A_STRIDE + 3 * B_STRIDE)

__global__ __launch_bounds__(256, 2) void k1_gemm(
    const float* __restrict__ seq, const float* __restrict__ seq_e,
    const float* __restrict__ seq_t, const float* __restrict__ bh)
{
    extern __shared__ float dsm[];
    const uint32_t sb = smem_u32(dsm);

    const int m0 = (blockIdx.x >> 2) * 128;
    const int gix = blockIdx.x & 3;        // gate index (n-tile)
    const int n0 = gix * 128;
    const int tid = threadIdx.x;
    const int lane = tid & 31;
    const int warp = tid >> 5;
    const int wm = (warp >> 2) * 64;
    const int wn = (warp & 3) * 32;
    const int g4 = lane >> 2;
    const int l4 = lane & 3;

    const int arow = tid >> 3;          // 0..31
    const int acol = (tid & 7) * 4;     // 0..28
    const int brow = tid >> 5;          // 0..7
    const int bcol = (tid & 31) * 4;    // 0..124

    float acc[4][4][4];
    #pragma unroll
    for (int i = 0; i < 4; i++)
        #pragma unroll
        for (int j = 0; j < 4; j++)
            #pragma unroll
            for (int q = 0; q < 4; q++) acc[i][j][q] = 0.f;

    auto issue = [&](int c) {
        const int buf = c % 3;
        const float* Xs = (c < 4) ? seq : (c < 8) ? seq_e : seq_t;
        const int kb = (c & 3) * 32;
        #pragma unroll
        for (int i = 0; i < 4; i++)
            cpasync16(sb + buf * A_STRIDE + ((arow + 32 * i) * 36 + acol) * 4,
                      Xs + (size_t)(m0 + arow + 32 * i) * FF + kb + acol);
        #pragma unroll
        for (int i = 0; i < 4; i++)
            cpasync16(sb + B_BASE + buf * B_STRIDE + ((brow + 8 * i) * 132 + bcol) * 4,
                      g_WiR + (size_t)(c * 32 + brow + 8 * i) * GG + n0 + bcol);
        cpcommit();
    };

    issue(0);
    issue(1);
    cpwait<1>();            // chunk 0 complete (chunk 1 still in flight)
    __syncthreads();

    for (int c = 0; c < 12; c++) {
        if (c + 2 < 12) issue(c + 2);      // writes buf (c-1)%3: free since last sync

        const float* As = dsm + (c % 3) * (A_STRIDE / 4);
        const float* Bs = dsm + (B_BASE / 4) + (c % 3) * (B_STRIDE / 4);
        #pragma unroll
        for (int k8 = 0; k8 < 32; k8 += 8) {
            uint32_t af[4][4];
            #pragma unroll
            for (int i = 0; i < 4; i++) {
                int row = wm + i * 16 + g4;
                int col = k8 + l4;
                af[i][0] = __float_as_uint(As[row * 36 + col]);
                af[i][1] = __float_as_uint(As[(row + 8) * 36 + col]);
                af[i][2] = __float_as_uint(As[row * 36 + col + 4]);
                af[i][3] = __float_as_uint(As[(row + 8) * 36 + col + 4]);
            }
            uint32_t bf2[4][2];
            #pragma unroll
            for (int j = 0; j < 4; j++) {
                int nn = wn + j * 8 + g4;
                bf2[j][0] = __float_as_uint(Bs[(k8 + l4) * 132 + nn]);
                bf2[j][1] = __float_as_uint(Bs[(k8 + 4 + l4) * 132 + nn]);
            }
            #pragma unroll
            for (int i = 0; i < 4; i++)
                #pragma unroll
                for (int j = 0; j < 4; j++)
                    mma8(acc[i][j], af[i], bf2[j]);
        }
        if (c + 1 < 12) {
            if (c + 2 < 12) cpwait<1>(); else cpwait<0>();  // chunk c+1 resident
            __syncthreads();
        }
    }

    // epilogue: + bh, permuted column store
    // f = wn + j*8 + l4*2; cperm = (f>>4)*64 + (gix*2 + ((f>>3)&1))*8 + (f&7)
    #pragma unroll
    for (int i = 0; i < 4; i++) {
        int gr = m0 + wm + i * 16 + g4;
        #pragma unroll
        for (int j = 0; j < 4; j++) {
            int f = wn + j * 8 + l4 * 2;
            int cperm = (f >> 4) * 64 + (gix * 2 + ((f >> 3) & 1)) * 8 + (f & 7);
            float bv0 = bh[n0 + f], bv1 = bh[n0 + f + 1];
            float2 v0 = make_float2(acc[i][j][0] + bv0, acc[i][j][1] + bv1);
            float2 v1 = make_float2(acc[i][j][2] + bv0, acc[i][j][3] + bv1);
            *(float2*)(g_Z + (size_t)gr * GG + cperm) = v0;
            *(float2*)(g_Z + (size_t)(gr + 8) * GG + cperm) = v1;
        }
    }
}

// ---------------------------------------------------------------------------
// k2: recurrent LSTM, 32 batch rows per CTA, register gates, c in registers,
// h double-buffered in SMEM (1 barrier/step), Wh register-double-buffered,
// Z rows prefetched one step ahead.
// ---------------------------------------------------------------------------
#define K2_SMEM ((2 * 32 * 132 + 32 * 128 + 32 * 128) * 4)

__global__ __launch_bounds__(256, 1) void k2_lstm(
    const float* __restrict__ src,
    const float* __restrict__ W1, const float* __restrict__ b1,
    const float* __restrict__ W2, const float* __restrict__ b2,
    float* __restrict__ out)
{
    extern __shared__ float sm[];
    float* h2 = sm;                   // 2 buffers of 32 x 132
    float* s_src = sm + 2 * 32 * 132; // 32 x 128
    float* s_hid = s_src + 32 * 128;  // 32 x 128

    const int b0 = blockIdx.x * 32;
    const int tid = threadIdx.x;
    const int lane = tid & 31;
    const int warp = tid >> 5;
    const int g4 = lane >> 2;
    const int l4 = lane & 3;

    for (int p = tid; p < 32 * 132; p += 256) h2[p] = 0.f;  // buf0 = h(-1) = 0
    __syncthreads();

    const float2* whf = (const float2*)g_WhF;
    const int wbase = warp * 8;   // n8 base for this warp

    float c_reg[2][2][4];
    #pragma unroll
    for (int i = 0; i < 2; i++)
        #pragma unroll
        for (int jh = 0; jh < 2; jh++)
            #pragma unroll
            for (int q = 0; q < 4; q++) c_reg[i][jh][q] = 0.f;

    // Z prefetch registers (step t's values, loaded during step t-1)
    float2 zreg[2][8][2];
    #pragma unroll
    for (int i = 0; i < 2; i++) {
        const float* z0 = g_Z + ((size_t)(b0 + i * 16 + g4) * TT + 0) * GG + warp * 64;
        const float* z1 = g_Z + ((size_t)(b0 + i * 16 + g4 + 8) * TT + 0) * GG + warp * 64;
        #pragma unroll
        for (int j = 0; j < 8; j++) {
            zreg[i][j][0] = *(const float2*)(z0 + j * 8 + l4 * 2);
            zreg[i][j][1] = *(const float2*)(z1 + j * 8 + l4 * 2);
        }
    }

    for (int t = 0; t < TT; t++) {
        const float* hcur = h2 + (t & 1) * (32 * 132);
        float* hnxt = h2 + ((t + 1) & 1) * (32 * 132);

        // --- acc init from prefetched Z ---
        float acc[2][8][4];
        #pragma unroll
        for (int i = 0; i < 2; i++)
            #pragma unroll
            for (int j = 0; j < 8; j++) {
                acc[i][j][0] = zreg[i][j][0].x; acc[i][j][1] = zreg[i][j][0].y;
                acc[i][j][2] = zreg[i][j][1].x; acc[i][j][3] = zreg[i][j][1].y;
            }

        // --- issue Z prefetch for next step (hidden under the mma loop) ---
        {
            const int tn = (t + 1 < TT) ? t + 1 : TT - 1;
            #pragma unroll
            for (int i = 0; i < 2; i++) {
                const float* z0 = g_Z + ((size_t)(b0 + i * 16 + g4) * TT + tn) * GG + warp * 64;
                const float* z1 = g_Z + ((size_t)(b0 + i * 16 + g4 + 8) * TT + tn) * GG + warp * 64;
                #pragma unroll
                for (int j = 0; j < 8; j++) {
                    zreg[i][j][0] = *(const float2*)(z0 + j * 8 + l4 * 2);
                    zreg[i][j][1] = *(const float2*)(z1 + j * 8 + l4 * 2);
                }
            }
        }

        // --- z += h @ Wh, Wh register-double-buffered ---
        float2 wreg[8];
        #pragma unroll
        for (int j = 0; j < 8; j++)
            wreg[j] = whf[(size_t)(wbase + j) * 32 + lane];

        #pragma unroll
        for (int kk16 = 0; kk16 < 16; kk16++) {
            float2 wnxt[8];
            if (kk16 < 15) {
                #pragma unroll
                for (int j = 0; j < 8; j++)
                    wnxt[j] = whf[(size_t)((kk16 + 1) * 64 + wbase + j) * 32 + lane];
            }
            const int kk = kk16 * 8;
            uint32_t af[2][4];
            #pragma unroll
            for (int i = 0; i < 2; i++) {
                int row = i * 16 + g4;
                af[i][0] = __float_as_uint(hcur[row * 132 + kk + l4]);
                af[i][1] = __float_as_uint(hcur[(row + 8) * 132 + kk + l4]);
                af[i][2] = __float_as_uint(hcur[row * 132 + kk + 4 + l4]);
                af[i][3] = __float_as_uint(hcur[(row + 8) * 132 + kk + 4 + l4]);
            }
            #pragma unroll
            for (int j = 0; j < 8; j++) {
                uint32_t bf2[2] = { __float_as_uint(wreg[j].x), __float_as_uint(wreg[j].y) };
                mma8(acc[0][j], af[0], bf2);
                mma8(acc[1][j], af[1], bf2);
            }
            if (kk16 < 15) {
                #pragma unroll
                for (int j = 0; j < 8; j++) wreg[j] = wnxt[j];
            }
        }

        // --- gates in registers: j = gate*2 + jh ---
        #pragma unroll
        for (int i = 0; i < 2; i++) {
            int r0 = i * 16 + g4;
            #pragma unroll
            for (int jh = 0; jh < 2; jh++) {
                float hv[4];
                #pragma unroll
                for (int q = 0; q < 4; q++) {
                    float zi = acc[i][0 + jh][q];
                    float zf = acc[i][2 + jh][q];
                    float zg = acc[i][4 + jh][q];
                    float zo = acc[i][6 + jh][q];
                    float co = c_reg[i][jh][q];
                    float cn = sigm_f(zf) * co + sigm_f(zi) * tanh_f(zg);
                    hv[q] = sigm_f(zo) * tanh_f(cn);
                    c_reg[i][jh][q] = cn;
                }
                int fb = warp * 16 + jh * 8 + l4 * 2;
                *(float2*)(hnxt + r0 * 132 + fb) =
                    make_float2(tf32r(hv[0]), tf32r(hv[1]));
                *(float2*)(hnxt + (r0 + 8) * 132 + fb) =
                    make_float2(tf32r(hv[2]), tf32r(hv[3]));
            }
        }
        __syncthreads();
    }

    // ---------------- fused merge MLP: out = relu([hn|src]@W1+b1)@W2+b2 ----
    const float* hfin = h2;  // t=127 wrote buffer 0
    for (int p = tid; p < 32 * 128; p += 256) {
        int row = p >> 7, fc = p & 127;
        s_src[p] = src[(size_t)(b0 + row) * FF + fc];
    }
    __syncthreads();

    const int col = tid & 127;
    const int rb = (tid >> 7) * 16;
    float a1[16];
    #pragma unroll
    for (int r = 0; r < 16; r++) a1[r] = b1[col];
    for (int k = 0; k < 128; k++) {
        float wv = W1[k * 128 + col];
        #pragma unroll
        for (int r = 0; r < 16; r++) a1[r] += hfin[(rb + r) * 132 + k] * wv;
    }
    for (int k = 0; k < 128; k++) {
        float wv = W1[(128 + k) * 128 + col];
        #pragma unroll
        for (int r = 0; r < 16; r++) a1[r] += s_src[(rb + r) * 128 + k] * wv;
    }
    #pragma unroll
    for (int r = 0; r < 16; r++) a1[r] = fmaxf(a1[r], 0.f);

    #pragma unroll
    for (int r = 0; r < 16; r++) s_hid[(rb + r) * 128 + col] = a1[r];
    __syncthreads();

    float a2[16];
    #pragma unroll
    for (int r = 0; r < 16; r++) a2[r] = b2[col];
    for (int k = 0; k < 128; k++) {
        float wv = W2[k * 128 + col];
        #pragma unroll
        for (int r = 0; r < 16; r++) a2[r] += s_hid[(rb + r) * 128 + k] * wv;
    }
    #pragma unroll
    for (int r = 0; r < 16; r++)
        out[(size_t)(b0 + rb + r) * FF + col] = a2[r];
}

// ---------------------------------------------------------------------------
// launch
// inputs: 0 src, 1 src_t(unused), 2 seq, 3 seq_t, 4 seq_e, 5 mask(unused),
//         6 Wi, 7 Wh, 8 bh, 9 W1, 10 b1, 11 W2, 12 b2
// ---------------------------------------------------------------------------
extern "C" void kernel_launch(void* const* d_in, const int* in_sizes, int n_in,
                              void* d_out, int out_size)
{
    const float* src   = (const float*)d_in[0];
    const float* seq   = (const float*)d_in[2];
    const float* seq_t = (const float*)d_in[3];
    const float* seq_e = (const float*)d_in[4];
    const float* Wi    = (const float*)d_in[6];
    const float* Wh    = (const float*)d_in[7];
    const float* bh    = (const float*)d_in[8];
    const float* W1    = (const float*)d_in[9];
    const float* b1    = (const float*)d_in[10];
    const float* W2    = (const float*)d_in[11];
    const float* b2    = (const float*)d_in[12];
    float* out = (float*)d_out;

    // capture-slot alignment: ncu grabs the 4th launch -> k1_gemm this round
    dAlign1<<<1, 32>>>();
    dAlign2<<<1, 32>>>();

    k0_prep<<<(AA * GG + 255) / 256, 256>>>(Wi, Wh);

    cudaFuncSetAttribute(k1_gemm, cudaFuncAttributeMaxDynamicSharedMemorySize, K1_SMEM);
    k1_gemm<<<(BT_ / 128) * 4, 256, K1_SMEM>>>(seq, seq_e, seq_t, bh);

    cudaFuncSetAttribute(k2_lstm, cudaFuncAttributeMaxDynamicSharedMemorySize, K2_SMEM);
    k2_lstm<<<BB / 32, 256, K2_SMEM>>>(src, W1, b1, W2, b2, out);
}